// round 3
// baseline (speedup 1.0000x reference)
#include <cuda_runtime.h>
#include <math.h>

// Problem dims (fixed by the reference): x[8,1024,1024], w1[4096,1024], w2[1024,4096]
#define DIM 1024
#define HID 4096
#define TOK 8192   // B*S = 8*1024

// ---------------- scratch (device globals; no allocations allowed) ----------------
__device__ float g_xn[(size_t)TOK * DIM];     // LN1 output        32 MB
__device__ float g_h [(size_t)TOK * HID];     // GEMM1/GELU/LN2   128 MB
__device__ float g_t1[(size_t)HID * DIM];     // ternary w1 (as float -1/0/1)  16 MB
__device__ float g_t2[(size_t)DIM * HID];     // ternary w2                    16 MB
__device__ float g_partial[2][256];           // abs-sum partials
__device__ float g_scale[2];                  // 1/mean|w|  (quantization scale)
__device__ float g_mul[2];                    // mean|w| clipped (epilogue multiplier)

// ---------------- helpers ----------------
__device__ __forceinline__ float warp_sum(float v) {
#pragma unroll
    for (int o = 16; o > 0; o >>= 1) v += __shfl_xor_sync(0xffffffffu, v, o);
    return v;
}

// Deterministic block reduce of one float per thread (256 threads).
__device__ __forceinline__ float block_sum_256(float v) {
    __shared__ float sh[8];
    v = warp_sum(v);
    if ((threadIdx.x & 31) == 0) sh[threadIdx.x >> 5] = v;
    __syncthreads();
    float tot = 0.f;
    if (threadIdx.x == 0) {
#pragma unroll
        for (int i = 0; i < 8; i++) tot += sh[i];
        sh[0] = tot;
    }
    __syncthreads();
    tot = sh[0];
    __syncthreads();
    return tot;
}

// ---------------- stage 0: abs-mean of weights (two-stage, deterministic) ----------------
__global__ void absmean_partial_kernel(const float* __restrict__ w, int n, int slot) {
    float s = 0.f;
    int stride = gridDim.x * blockDim.x;
    for (int i = blockIdx.x * blockDim.x + threadIdx.x; i < n; i += stride)
        s += fabsf(w[i]);
    s = block_sum_256(s);
    if (threadIdx.x == 0) g_partial[slot][blockIdx.x] = s;
}

__global__ void finalize_scales_kernel(int n1, int n2) {
    for (int slot = 0; slot < 2; slot++) {
        float v = g_partial[slot][threadIdx.x];
        float tot = block_sum_256(v);
        if (threadIdx.x == 0) {
            float mean = tot / (float)(slot == 0 ? n1 : n2);
            mean = fmaxf(mean, 1e-5f);          // jnp.clip(mean, 1e-5)
            g_mul[slot]   = mean;               // = 1/scale
            g_scale[slot] = 1.0f / mean;        // = scale
        }
        __syncthreads();
    }
}

// ---------------- stage 1: ternary quantization ----------------
__global__ void quant_kernel(const float* __restrict__ w, float* __restrict__ t,
                             const float* __restrict__ scalep, int n) {
    float s = *scalep;
    int stride = gridDim.x * blockDim.x;
    for (int i = blockIdx.x * blockDim.x + threadIdx.x; i < n; i += stride) {
        float v = rintf(w[i] * s);              // round half-to-even, matches jnp.round
        t[i] = fmaxf(-1.f, fminf(1.f, v));
    }
}

// ---------------- LayerNorm (one block / row; safe in-place) ----------------
__global__ __launch_bounds__(256) void ln_kernel(const float* __restrict__ x,
                                                 float* __restrict__ y,
                                                 const float* __restrict__ gamma,
                                                 const float* __restrict__ beta, int D) {
    const int row = blockIdx.x;
    const float* xr = x + (size_t)row * D;
    float* yr = y + (size_t)row * D;
    float s = 0.f, sq = 0.f;
    for (int i = threadIdx.x; i < D; i += blockDim.x) {
        float v = xr[i];
        s += v; sq += v * v;
    }
    __shared__ float sh[16];
    float ws = warp_sum(s), wq = warp_sum(sq);
    if ((threadIdx.x & 31) == 0) { sh[threadIdx.x >> 5] = ws; sh[8 + (threadIdx.x >> 5)] = wq; }
    __syncthreads();
    __shared__ float s_mu, s_rstd;
    if (threadIdx.x == 0) {
        float ts = 0.f, tq = 0.f;
#pragma unroll
        for (int i = 0; i < 8; i++) { ts += sh[i]; tq += sh[8 + i]; }
        float mu = ts / (float)D;
        float var = tq / (float)D - mu * mu;
        s_mu = mu;
        s_rstd = rsqrtf(var + 1e-5f);
    }
    __syncthreads();
    float mu = s_mu, rstd = s_rstd;
    for (int i = threadIdx.x; i < D; i += blockDim.x) {
        yr[i] = (xr[i] - mu) * rstd * gamma[i] + beta[i];
    }
}

// ---------------- GEMM: C[M,N] = (A[M,K] . B[N,K]^T) * mul + bias, optional exact GELU ------
// Both operands K-contiguous. 128x128 block tile, BK=16, 8x8 per thread, 256 threads.
#define BM 128
#define BN 128
#define BKT 16

__global__ __launch_bounds__(256) void gemm_tern_kernel(
    const float* __restrict__ A, const float* __restrict__ B,
    const float* __restrict__ bias, const float* __restrict__ mulp,
    float* __restrict__ C, int M, int N, int K, int do_gelu)
{
    __shared__ float As[BKT][BM];
    __shared__ float Bs[BKT][BN];
    const int bm = blockIdx.y * BM;
    const int bn = blockIdx.x * BN;
    const int tid = threadIdx.x;
    const int tr = tid >> 4;   // 0..15
    const int tc = tid & 15;   // 0..15

    float acc[8][8];
#pragma unroll
    for (int i = 0; i < 8; i++)
#pragma unroll
        for (int j = 0; j < 8; j++) acc[i][j] = 0.f;

    const float mul = *mulp;

    for (int k0 = 0; k0 < K; k0 += BKT) {
        // Load A & B tiles: 128 rows x 16 cols each = 512 float4, 2 per thread per tile
#pragma unroll
        for (int it = 0; it < 2; it++) {
            int idx = tid + it * 256;           // 0..511
            int row = idx >> 2;                 // 4 float4 per row
            int c4  = (idx & 3) << 2;
            float4 va = *reinterpret_cast<const float4*>(A + (size_t)(bm + row) * K + k0 + c4);
            As[c4 + 0][row] = va.x; As[c4 + 1][row] = va.y;
            As[c4 + 2][row] = va.z; As[c4 + 3][row] = va.w;
            float4 vb = *reinterpret_cast<const float4*>(B + (size_t)(bn + row) * K + k0 + c4);
            Bs[c4 + 0][row] = vb.x; Bs[c4 + 1][row] = vb.y;
            Bs[c4 + 2][row] = vb.z; Bs[c4 + 3][row] = vb.w;
        }
        __syncthreads();

#pragma unroll
        for (int k = 0; k < BKT; k++) {
            float4 a0 = *reinterpret_cast<const float4*>(&As[k][tr << 2]);
            float4 a1 = *reinterpret_cast<const float4*>(&As[k][64 + (tr << 2)]);
            float4 b0 = *reinterpret_cast<const float4*>(&Bs[k][tc << 2]);
            float4 b1 = *reinterpret_cast<const float4*>(&Bs[k][64 + (tc << 2)]);
            float a[8] = {a0.x, a0.y, a0.z, a0.w, a1.x, a1.y, a1.z, a1.w};
            float b[8] = {b0.x, b0.y, b0.z, b0.w, b1.x, b1.y, b1.z, b1.w};
#pragma unroll
            for (int i = 0; i < 8; i++)
#pragma unroll
                for (int j = 0; j < 8; j++)
                    acc[i][j] = fmaf(a[i], b[j], acc[i][j]);
        }
        __syncthreads();
    }

    // Epilogue: *mul + bias (+ exact GELU)
#pragma unroll
    for (int i = 0; i < 8; i++) {
        int gr = bm + ((i < 4) ? (tr * 4 + i) : (64 + tr * 4 + i - 4));
#pragma unroll
        for (int j = 0; j < 8; j++) {
            int gc = bn + ((j < 4) ? (tc * 4 + j) : (64 + tc * 4 + j - 4));
            float v = acc[i][j] * mul + bias[gc];
            if (do_gelu) v = 0.5f * v * (1.0f + erff(v * 0.70710678118654752f));
            C[(size_t)gr * N + gc] = v;
        }
    }
}

// ---------------- launcher ----------------
extern "C" void kernel_launch(void* const* d_in, const int* in_sizes, int n_in,
                              void* d_out, int out_size)
{
    const float* x    = (const float*)d_in[0];
    const float* ln1g = (const float*)d_in[1];
    const float* ln1b = (const float*)d_in[2];
    const float* w1   = (const float*)d_in[3];
    const float* b1   = (const float*)d_in[4];
    const float* ln2g = (const float*)d_in[5];
    const float* ln2b = (const float*)d_in[6];
    const float* w2   = (const float*)d_in[7];
    const float* b2   = (const float*)d_in[8];
    float* out = (float*)d_out;

    float *xn, *h, *t1, *t2, *scale, *mul;
    cudaGetSymbolAddress((void**)&xn,    g_xn);
    cudaGetSymbolAddress((void**)&h,     g_h);
    cudaGetSymbolAddress((void**)&t1,    g_t1);
    cudaGetSymbolAddress((void**)&t2,    g_t2);
    cudaGetSymbolAddress((void**)&scale, g_scale);
    cudaGetSymbolAddress((void**)&mul,   g_mul);

    // 1) weight abs-means -> scales (deterministic two-stage reduction)
    absmean_partial_kernel<<<256, 256>>>(w1, HID * DIM, 0);
    absmean_partial_kernel<<<256, 256>>>(w2, DIM * HID, 1);
    finalize_scales_kernel<<<1, 256>>>(HID * DIM, DIM * HID);

    // 2) ternary quantization of both weight matrices
    quant_kernel<<<512, 256>>>(w1, t1, scale + 0, HID * DIM);
    quant_kernel<<<512, 256>>>(w2, t2, scale + 1, DIM * HID);

    // 3) LN1
    ln_kernel<<<TOK, 256>>>(x, xn, ln1g, ln1b, DIM);

    // 4) GEMM1 + bias + exact GELU  (M=8192, N=4096, K=1024)
    gemm_tern_kernel<<<dim3(HID / BN, TOK / BM), 256>>>(xn, t1, b1, mul + 0, h,
                                                        TOK, HID, DIM, 1);

    // 5) LN2 (in-place on h)
    ln_kernel<<<TOK, 256>>>(h, h, ln2g, ln2b, HID);

    // 6) GEMM2 + bias  (M=8192, N=1024, K=4096)
    gemm_tern_kernel<<<dim3(DIM / BN, TOK / BM), 256>>>(h, t2, b2, mul + 1, out,
                                                        TOK, DIM, HID, 0);
}

// round 6
// speedup vs baseline: 6.8272x; 6.8272x over previous
#include <cuda_runtime.h>
#include <cuda_bf16.h>
#include <math.h>
#include <stdint.h>

// Problem dims (fixed): x[8,1024,1024], w1[4096,1024], w2[1024,4096]
#define DIM 1024
#define HID 4096
#define TOK 8192   // B*S

// tcgen05 is an arch-SPECIFIC feature: only emit it in the sm_103a/sm_100a
// device pass. Other passes (compute_103 plain) get a correct SIMT fallback.
#if defined(__CUDA_ARCH_FEAT_SM103_ALL) || defined(__CUDA_ARCH_FEAT_SM100_ALL) || \
    defined(__CUDA_ARCH_FEAT_SM101_ALL) || defined(__CUDA_ARCH_FEAT_SM110_ALL)
#define TC_OK 1
#else
#define TC_OK 0
#endif

// ---------------- scratch (device globals; no allocations allowed) ----------------
__device__ __nv_bfloat16 g_xhi[(size_t)TOK * DIM];   // LN1 out, bf16 hi   16MB
__device__ __nv_bfloat16 g_xlo[(size_t)TOK * DIM];   // LN1 out, bf16 lo   16MB
__device__ float         g_h  [(size_t)TOK * HID];   // GEMM1+GELU out    128MB
__device__ __nv_bfloat16 g_hhi[(size_t)TOK * HID];   // LN2 out hi         64MB
__device__ __nv_bfloat16 g_hlo[(size_t)TOK * HID];   // LN2 out lo         64MB
__device__ __nv_bfloat16 g_t1 [(size_t)HID * DIM];   // ternary w1 bf16     8MB
__device__ __nv_bfloat16 g_t2 [(size_t)DIM * HID];   // ternary w2 bf16     8MB
__device__ float g_partial[2][256];
__device__ float g_scale[2];     // 1/mean|w|
__device__ float g_mul[2];       // mean|w| (epilogue multiplier)

// ---------------- small helpers ----------------
__device__ __forceinline__ float warp_sum(float v) {
#pragma unroll
    for (int o = 16; o > 0; o >>= 1) v += __shfl_xor_sync(0xffffffffu, v, o);
    return v;
}
__device__ __forceinline__ float block_sum_256(float v) {
    __shared__ float sh[8];
    v = warp_sum(v);
    if ((threadIdx.x & 31) == 0) sh[threadIdx.x >> 5] = v;
    __syncthreads();
    float tot = 0.f;
    if (threadIdx.x == 0) {
#pragma unroll
        for (int i = 0; i < 8; i++) tot += sh[i];
        sh[0] = tot;
    }
    __syncthreads();
    tot = sh[0];
    __syncthreads();
    return tot;
}

__device__ __forceinline__ uint32_t smem_u32(const void* p) {
    uint32_t a;
    asm("{ .reg .u64 t; cvta.to.shared.u64 t, %1; cvt.u32.u64 %0, t; }" : "=r"(a) : "l"(p));
    return a;
}
#define SW128(o) ((o) ^ (((o) >> 3) & 0x70))

// SW128 K-major smem descriptor (layout=2, version=1, SBO=64, LBO=1)
static constexpr uint64_t SMEM_DESC_BASE =
    (uint64_t(2) << 61) | (uint64_t(1) << 46) | (uint64_t(64) << 32) | (uint64_t(1) << 16);
__device__ __forceinline__ uint64_t make_desc(uint32_t addr) {
    return SMEM_DESC_BASE | ((uint64_t)(addr >> 4) & 0x3FFF);
}

// ---------------- PTX wrappers (cp.async / mbarrier are NOT arch-specific) -------
__device__ __forceinline__ void cp16(uint32_t dst, const void* src) {
    asm volatile("cp.async.cg.shared.global [%0], [%1], 16;" :: "r"(dst), "l"(src));
}
__device__ __forceinline__ void cp_commit() {
    asm volatile("cp.async.commit_group;" ::: "memory");
}
template <int N>
__device__ __forceinline__ void cp_wait() {
    asm volatile("cp.async.wait_group %0;" :: "n"(N) : "memory");
}
__device__ __forceinline__ void mbar_init(uint32_t a, uint32_t cnt) {
    asm volatile("mbarrier.init.shared.b64 [%0], %1;" :: "r"(a), "r"(cnt) : "memory");
}
__device__ __forceinline__ void mbar_wait(uint32_t a, uint32_t parity) {
    asm volatile(
        "{\n\t.reg .pred P;\n\t"
        "MW_%=:\n\t"
        "mbarrier.try_wait.parity.acquire.cta.shared::cta.b64 P, [%0], %1;\n\t"
        "@!P bra MW_%=;\n\t}"
        :: "r"(a), "r"(parity) : "memory");
}
#define FENCE_ASYNC() asm volatile("fence.proxy.async.shared::cta;" ::: "memory")

#if TC_OK
// ---- tcgen05 wrappers (guarded) ----
__device__ __forceinline__ void tc_commit(uint32_t mbar) {
    asm volatile(
        "tcgen05.commit.cta_group::1.mbarrier::arrive::one.shared::cluster.b64 [%0];"
        :: "r"(mbar) : "memory");
}
__device__ __forceinline__ void mma_f16_ss(uint32_t d, uint64_t a_desc, uint64_t b_desc,
                                           uint32_t idesc, uint32_t accum) {
    asm volatile(
        "{\n\t.reg .pred p;\n\t"
        "setp.ne.u32 p, %4, 0;\n\t"
        "tcgen05.mma.cta_group::1.kind::f16 [%0], %1, %2, %3, {%5, %5, %5, %5}, p;\n\t}"
        :: "r"(d), "l"(a_desc), "l"(b_desc), "r"(idesc), "r"(accum), "r"(0u)
        : "memory");
}
#define TC_ALLOC(saddr, n) \
    asm volatile("tcgen05.alloc.cta_group::1.sync.aligned.shared::cta.b32 [%0], %1;" \
                 :: "r"(saddr), "r"((uint32_t)(n)) : "memory")
#define TC_RELINQ() \
    asm volatile("tcgen05.relinquish_alloc_permit.cta_group::1.sync.aligned;")
#define TC_DEALLOC(t, n) \
    asm volatile("tcgen05.dealloc.cta_group::1.sync.aligned.b32 %0, %1;" :: "r"(t), "r"((uint32_t)(n)))
#define TC_FENCE_AFTER()  asm volatile("tcgen05.fence::after_thread_sync;" ::: "memory")
#define TC_WAIT_LD()      asm volatile("tcgen05.wait::ld.sync.aligned;" ::: "memory")

#define LDTM_X32(r, addr) \
    asm volatile( \
        "tcgen05.ld.sync.aligned.32x32b.x32.b32 " \
        "{%0, %1, %2, %3, %4, %5, %6, %7, " \
        " %8, %9, %10, %11, %12, %13, %14, %15, " \
        " %16, %17, %18, %19, %20, %21, %22, %23, " \
        " %24, %25, %26, %27, %28, %29, %30, %31}, [%32];" \
        : "=r"((r)[0]),  "=r"((r)[1]),  "=r"((r)[2]),  "=r"((r)[3]), \
          "=r"((r)[4]),  "=r"((r)[5]),  "=r"((r)[6]),  "=r"((r)[7]), \
          "=r"((r)[8]),  "=r"((r)[9]),  "=r"((r)[10]), "=r"((r)[11]), \
          "=r"((r)[12]), "=r"((r)[13]), "=r"((r)[14]), "=r"((r)[15]), \
          "=r"((r)[16]), "=r"((r)[17]), "=r"((r)[18]), "=r"((r)[19]), \
          "=r"((r)[20]), "=r"((r)[21]), "=r"((r)[22]), "=r"((r)[23]), \
          "=r"((r)[24]), "=r"((r)[25]), "=r"((r)[26]), "=r"((r)[27]), \
          "=r"((r)[28]), "=r"((r)[29]), "=r"((r)[30]), "=r"((r)[31]) \
        : "r"(addr))
#endif  // TC_OK

// ---------------- stage 0: abs-mean of weights ----------------
__global__ void absmean_partial_kernel(const float* __restrict__ w, int n, int slot) {
    float s = 0.f;
    int stride = gridDim.x * blockDim.x;
    for (int i = blockIdx.x * blockDim.x + threadIdx.x; i < n; i += stride)
        s += fabsf(w[i]);
    s = block_sum_256(s);
    if (threadIdx.x == 0) g_partial[slot][blockIdx.x] = s;
}
__global__ void finalize_scales_kernel(int n1, int n2) {
    for (int slot = 0; slot < 2; slot++) {
        float v = g_partial[slot][threadIdx.x];
        float tot = block_sum_256(v);
        if (threadIdx.x == 0) {
            float mean = tot / (float)(slot == 0 ? n1 : n2);
            mean = fmaxf(mean, 1e-5f);
            g_mul[slot]   = mean;
            g_scale[slot] = 1.0f / mean;
        }
        __syncthreads();
    }
}

// ---------------- stage 1: ternary quantization -> bf16 ----------------
__global__ void quant_kernel(const float* __restrict__ w, __nv_bfloat16* __restrict__ t,
                             const float* __restrict__ scalep, int n) {
    float s = *scalep;
    int stride = gridDim.x * blockDim.x;
    for (int i = blockIdx.x * blockDim.x + threadIdx.x; i < n; i += stride) {
        float v = rintf(w[i] * s);              // round half-to-even (jnp.round)
        v = fmaxf(-1.f, fminf(1.f, v));
        t[i] = __float2bfloat16(v);             // exact for {-1,0,1}
    }
}

// ---------------- LayerNorm with bf16 hi/lo split output ----------------
__global__ __launch_bounds__(256) void ln_split_kernel(
    const float* __restrict__ x, __nv_bfloat16* __restrict__ hi, __nv_bfloat16* __restrict__ lo,
    const float* __restrict__ gamma, const float* __restrict__ beta, int D)
{
    const int row = blockIdx.x;
    const float* xr = x + (size_t)row * D;
    float s = 0.f, sq = 0.f;
    for (int i = threadIdx.x; i < D; i += blockDim.x) {
        float v = xr[i];
        s += v; sq += v * v;
    }
    __shared__ float sh[16];
    float ws = warp_sum(s), wq = warp_sum(sq);
    if ((threadIdx.x & 31) == 0) { sh[threadIdx.x >> 5] = ws; sh[8 + (threadIdx.x >> 5)] = wq; }
    __syncthreads();
    __shared__ float s_mu, s_rstd;
    if (threadIdx.x == 0) {
        float ts = 0.f, tq = 0.f;
#pragma unroll
        for (int i = 0; i < 8; i++) { ts += sh[i]; tq += sh[8 + i]; }
        float mu = ts / (float)D;
        float var = tq / (float)D - mu * mu;
        s_mu = mu;
        s_rstd = rsqrtf(var + 1e-5f);
    }
    __syncthreads();
    float mu = s_mu, rstd = s_rstd;
    for (int i = threadIdx.x; i < D; i += blockDim.x) {
        float v = (xr[i] - mu) * rstd * gamma[i] + beta[i];
        __nv_bfloat16 h16 = __float2bfloat16(v);
        hi[(size_t)row * D + i] = h16;
        lo[(size_t)row * D + i] = __float2bfloat16(v - __bfloat162float(h16));
    }
}

// ---------------- GEMM: C[M,N] = ((Ahi+Alo)[M,K] . B[N,K]^T)*mul + bias (+GELU) ----------
#define BM 128
#define BN 128
#define BK 64
#define TILE_BYTES   16384                 // 128 rows x 128B
#define STAGE_BYTES  (3 * TILE_BYTES)      // Ahi, Alo, B
#define SM_TMEMPTR   (2 * STAGE_BYTES)     // 98304
#define SM_MBAR0     (SM_TMEMPTR + 8)
#define SM_MBAR1     (SM_TMEMPTR + 16)
#define SMEM_TOTAL   (SM_TMEMPTR + 64)
// idesc: f32 accum, bf16 A/B, N=128, M=128
#define MMA_IDESC 0x8200490u

__device__ __forceinline__ void load_chunk(
    const __nv_bfloat16* __restrict__ Ahi, const __nv_bfloat16* __restrict__ Alo,
    const __nv_bfloat16* __restrict__ Bt, int K, int bm, int bn, int k0, uint32_t sbase)
{
    int t = threadIdx.x;
#pragma unroll
    for (int i = 0; i < 4; i++) {
        int idx = t + (i << 8);
        int row = idx >> 3;       // 0..127
        int c   = idx & 7;        // 16B chunk in row
        uint32_t sw = SW128(row * 128 + c * 16);
        size_t eoff_a = (size_t)(bm + row) * K + k0 + c * 8;
        size_t eoff_b = (size_t)(bn + row) * K + k0 + c * 8;
        cp16(sbase + sw,                  Ahi + eoff_a);
        cp16(sbase + TILE_BYTES + sw,     Alo + eoff_a);
        cp16(sbase + 2 * TILE_BYTES + sw, Bt  + eoff_b);
    }
}

__global__ __launch_bounds__(256)
void gemm_tc_kernel(const __nv_bfloat16* __restrict__ Ahi, const __nv_bfloat16* __restrict__ Alo,
                    const __nv_bfloat16* __restrict__ Bt,  const float* __restrict__ bias,
                    const float* __restrict__ mulp, float* __restrict__ C,
                    int M, int N, int K, int do_gelu)
{
#if TC_OK
    // ======================= tcgen05 fast path (sm_103a) =======================
    extern __shared__ char smem[];
    const uint32_t sb  = smem_u32(smem);
    const int tid = threadIdx.x, wid = tid >> 5, lid = tid & 31;
    const int bm = blockIdx.y * BM, bn = blockIdx.x * BN;

    if (wid == 0) { TC_ALLOC(sb + SM_TMEMPTR, 128); TC_RELINQ(); }
    if (tid == 0) { mbar_init(sb + SM_MBAR0, 1); mbar_init(sb + SM_MBAR1, 1); }
    __syncthreads();
    uint32_t tmem;
    asm volatile("ld.shared.b32 %0, [%1];" : "=r"(tmem) : "r"(sb + SM_TMEMPTR));

    const float mul = *mulp;
    const int nk = K / BK;

    uint64_t ad[2], ld_[2], bd[2];
#pragma unroll
    for (int s = 0; s < 2; s++) {
        uint32_t base = sb + s * STAGE_BYTES;
        ad[s]  = make_desc(base);
        ld_[s] = make_desc(base + TILE_BYTES);
        bd[s]  = make_desc(base + 2 * TILE_BYTES);
    }

    // prologue: chunks 0 and 1
    load_chunk(Ahi, Alo, Bt, K, bm, bn, 0, sb);                cp_commit();
    load_chunk(Ahi, Alo, Bt, K, bm, bn, BK, sb + STAGE_BYTES); cp_commit();

    int wcnt0 = 0, wcnt1 = 0;
    for (int i = 0; i < nk; i++) {
        const int b = i & 1;
        if (i + 1 < nk) cp_wait<1>(); else cp_wait<0>();
        FENCE_ASYNC();
        __syncthreads();
        if (tid == 0) {
#pragma unroll
            for (int j = 0; j < 4; j++) {
                mma_f16_ss(tmem, ad[b]  + j * 2, bd[b] + j * 2, MMA_IDESC, (i > 0) || (j > 0));
                mma_f16_ss(tmem, ld_[b] + j * 2, bd[b] + j * 2, MMA_IDESC, 1u);
            }
            tc_commit(sb + SM_MBAR0 + b * 8);
        }
        if (i + 2 < nk) {
            if (b == 0) { mbar_wait(sb + SM_MBAR0, wcnt0 & 1); wcnt0++; }
            else        { mbar_wait(sb + SM_MBAR1, wcnt1 & 1); wcnt1++; }
            load_chunk(Ahi, Alo, Bt, K, bm, bn, (i + 2) * BK, sb + b * STAGE_BYTES);
            cp_commit();
        }
    }
    // drain both buffers' final MMAs (nk is even: 16 or 64)
    mbar_wait(sb + SM_MBAR0, wcnt0 & 1);
    mbar_wait(sb + SM_MBAR1, wcnt1 & 1);
    TC_FENCE_AFTER();

    // epilogue: warps 0-3 read their 32-row TMEM subpartitions
    if (wid < 4) {
        const int row = bm + wid * 32 + lid;
        float* crow = C + (size_t)row * N + bn;
#pragma unroll
        for (int c0 = 0; c0 < BN; c0 += 32) {
            uint32_t r[32];
            LDTM_X32(r, tmem + c0);
            TC_WAIT_LD();
#pragma unroll
            for (int j = 0; j < 32; j += 4) {
                float4 v4;
                float v0 = __uint_as_float(r[j + 0]) * mul + bias[bn + c0 + j + 0];
                float v1 = __uint_as_float(r[j + 1]) * mul + bias[bn + c0 + j + 1];
                float v2 = __uint_as_float(r[j + 2]) * mul + bias[bn + c0 + j + 2];
                float v3 = __uint_as_float(r[j + 3]) * mul + bias[bn + c0 + j + 3];
                if (do_gelu) {
                    v0 = 0.5f * v0 * (1.0f + erff(v0 * 0.70710678118654752f));
                    v1 = 0.5f * v1 * (1.0f + erff(v1 * 0.70710678118654752f));
                    v2 = 0.5f * v2 * (1.0f + erff(v2 * 0.70710678118654752f));
                    v3 = 0.5f * v3 * (1.0f + erff(v3 * 0.70710678118654752f));
                }
                v4.x = v0; v4.y = v1; v4.z = v2; v4.w = v3;
                *reinterpret_cast<float4*>(crow + c0 + j) = v4;
            }
        }
    }
    __syncthreads();
    if (wid == 0) TC_DEALLOC(tmem, 128);

#else
    // ============ SIMT fallback (correct on any arch; slower) ============
    extern __shared__ char smem[];
    float (*As)[BM] = reinterpret_cast<float (*)[BM]>(smem);              // [16][128]
    float (*Bs)[BN] = reinterpret_cast<float (*)[BN]>(smem + 16 * BM * 4);// [16][128]
    const int bm = blockIdx.y * BM;
    const int bn = blockIdx.x * BN;
    const int tid = threadIdx.x;
    const int tr = tid >> 4;   // 0..15
    const int tc = tid & 15;   // 0..15

    float acc[8][8];
#pragma unroll
    for (int i = 0; i < 8; i++)
#pragma unroll
        for (int j = 0; j < 8; j++) acc[i][j] = 0.f;

    const float mul = *mulp;

    for (int k0 = 0; k0 < K; k0 += 16) {
        // each thread loads 8 A elems (hi+lo) and 8 B elems
#pragma unroll
        for (int it = 0; it < 8; it++) {
            int idx = tid + it * 256;           // 0..2047
            int row = idx >> 4;                 // 0..127
            int c   = idx & 15;
            size_t ea = (size_t)(bm + row) * K + k0 + c;
            As[c][row] = __bfloat162float(Ahi[ea]) + __bfloat162float(Alo[ea]);
            size_t eb = (size_t)(bn + row) * K + k0 + c;
            Bs[c][row] = __bfloat162float(Bt[eb]);
        }
        __syncthreads();
#pragma unroll
        for (int k = 0; k < 16; k++) {
            float a[8], b[8];
#pragma unroll
            for (int i = 0; i < 4; i++) { a[i] = As[k][tr * 4 + i]; a[4 + i] = As[k][64 + tr * 4 + i]; }
#pragma unroll
            for (int j = 0; j < 4; j++) { b[j] = Bs[k][tc * 4 + j]; b[4 + j] = Bs[k][64 + tc * 4 + j]; }
#pragma unroll
            for (int i = 0; i < 8; i++)
#pragma unroll
                for (int j = 0; j < 8; j++)
                    acc[i][j] = fmaf(a[i], b[j], acc[i][j]);
        }
        __syncthreads();
    }

#pragma unroll
    for (int i = 0; i < 8; i++) {
        int gr = bm + ((i < 4) ? (tr * 4 + i) : (64 + tr * 4 + i - 4));
#pragma unroll
        for (int j = 0; j < 8; j++) {
            int gc = bn + ((j < 4) ? (tc * 4 + j) : (64 + tc * 4 + j - 4));
            float v = acc[i][j] * mul + bias[gc];
            if (do_gelu) v = 0.5f * v * (1.0f + erff(v * 0.70710678118654752f));
            C[(size_t)gr * N + gc] = v;
        }
    }
#endif
}

// ---------------- launcher ----------------
extern "C" void kernel_launch(void* const* d_in, const int* in_sizes, int n_in,
                              void* d_out, int out_size)
{
    const float* x    = (const float*)d_in[0];
    const float* ln1g = (const float*)d_in[1];
    const float* ln1b = (const float*)d_in[2];
    const float* w1   = (const float*)d_in[3];
    const float* b1   = (const float*)d_in[4];
    const float* ln2g = (const float*)d_in[5];
    const float* ln2b = (const float*)d_in[6];
    const float* w2   = (const float*)d_in[7];
    const float* b2   = (const float*)d_in[8];
    float* out = (float*)d_out;

    __nv_bfloat16 *xhi, *xlo, *hhi, *hlo, *t1, *t2;
    float *h, *scale, *mul;
    cudaGetSymbolAddress((void**)&xhi,   g_xhi);
    cudaGetSymbolAddress((void**)&xlo,   g_xlo);
    cudaGetSymbolAddress((void**)&h,     g_h);
    cudaGetSymbolAddress((void**)&hhi,   g_hhi);
    cudaGetSymbolAddress((void**)&hlo,   g_hlo);
    cudaGetSymbolAddress((void**)&t1,    g_t1);
    cudaGetSymbolAddress((void**)&t2,    g_t2);
    cudaGetSymbolAddress((void**)&scale, g_scale);
    cudaGetSymbolAddress((void**)&mul,   g_mul);

    static int smem_set = 0;
    if (!smem_set) {
        cudaFuncSetAttribute(gemm_tc_kernel, cudaFuncAttributeMaxDynamicSharedMemorySize,
                             SMEM_TOTAL);
        smem_set = 1;
    }

    // 1) scales (deterministic two-stage reduction)
    absmean_partial_kernel<<<256, 256>>>(w1, HID * DIM, 0);
    absmean_partial_kernel<<<256, 256>>>(w2, DIM * HID, 1);
    finalize_scales_kernel<<<1, 256>>>(HID * DIM, DIM * HID);

    // 2) ternary quantization -> bf16 (exact)
    quant_kernel<<<512, 256>>>(w1, t1, scale + 0, HID * DIM);
    quant_kernel<<<512, 256>>>(w2, t2, scale + 1, DIM * HID);

    // 3) LN1 -> bf16 hi/lo split
    ln_split_kernel<<<TOK, 256>>>(x, xhi, xlo, ln1g, ln1b, DIM);

    // 4) GEMM1 + bias + exact GELU  (tcgen05; M=8192, N=4096, K=1024)
    gemm_tc_kernel<<<dim3(HID / BN, TOK / BM), 256, SMEM_TOTAL>>>(
        xhi, xlo, t1, b1, mul + 0, h, TOK, HID, DIM, 1);

    // 5) LN2 -> bf16 hi/lo split
    ln_split_kernel<<<TOK, 256>>>(h, hhi, hlo, ln2g, ln2b, HID);

    // 6) GEMM2 + bias  (tcgen05; M=8192, N=1024, K=4096)
    gemm_tc_kernel<<<dim3(DIM / BN, TOK / BM), 256, SMEM_TOTAL>>>(
        hhi, hlo, t2, b2, mul + 1, out, TOK, DIM, HID, 0);
}

// round 7
// speedup vs baseline: 8.0322x; 1.1765x over previous
#include <cuda_runtime.h>
#include <cuda_bf16.h>
#include <math.h>
#include <stdint.h>

// Problem dims (fixed): x[8,1024,1024], w1[4096,1024], w2[1024,4096]
#define DIM 1024
#define HID 4096
#define TOK 8192   // B*S

// tcgen05 is arch-SPECIFIC: only emit in sm_103a/sm_100a-family passes.
#if defined(__CUDA_ARCH_FEAT_SM103_ALL) || defined(__CUDA_ARCH_FEAT_SM100_ALL) || \
    defined(__CUDA_ARCH_FEAT_SM101_ALL) || defined(__CUDA_ARCH_FEAT_SM110_ALL)
#define TC_OK 1
#else
#define TC_OK 0
#endif

// ---------------- scratch (device globals; no allocations allowed) ----------------
__device__ __nv_bfloat16 g_xhi[(size_t)TOK * DIM];
__device__ __nv_bfloat16 g_xlo[(size_t)TOK * DIM];
__device__ float         g_h  [(size_t)TOK * HID];
__device__ __nv_bfloat16 g_hhi[(size_t)TOK * HID];
__device__ __nv_bfloat16 g_hlo[(size_t)TOK * HID];
__device__ __nv_bfloat16 g_t1 [(size_t)HID * DIM];
__device__ __nv_bfloat16 g_t2 [(size_t)DIM * HID];
__device__ float g_partial[2][256];
__device__ float g_scale[2];     // 1/mean|w|
__device__ float g_mul[2];       // mean|w| (epilogue multiplier)

// ---------------- small helpers ----------------
__device__ __forceinline__ float warp_sum(float v) {
#pragma unroll
    for (int o = 16; o > 0; o >>= 1) v += __shfl_xor_sync(0xffffffffu, v, o);
    return v;
}
__device__ __forceinline__ float block_sum_256(float v) {
    __shared__ float sh[8];
    v = warp_sum(v);
    if ((threadIdx.x & 31) == 0) sh[threadIdx.x >> 5] = v;
    __syncthreads();
    float tot = 0.f;
    if (threadIdx.x == 0) {
#pragma unroll
        for (int i = 0; i < 8; i++) tot += sh[i];
        sh[0] = tot;
    }
    __syncthreads();
    tot = sh[0];
    __syncthreads();
    return tot;
}
__device__ __forceinline__ uint32_t smem_u32(const void* p) {
    uint32_t a;
    asm("{ .reg .u64 t; cvta.to.shared.u64 t, %1; cvt.u32.u64 %0, t; }" : "=r"(a) : "l"(p));
    return a;
}
#define SW128(o) ((o) ^ (((o) >> 3) & 0x70))

// SW128 K-major smem descriptor (layout=2, version=1, SBO=64, LBO=1)
static constexpr uint64_t SMEM_DESC_BASE =
    (uint64_t(2) << 61) | (uint64_t(1) << 46) | (uint64_t(64) << 32) | (uint64_t(1) << 16);
__device__ __forceinline__ uint64_t make_desc(uint32_t addr) {
    return SMEM_DESC_BASE | ((uint64_t)(addr >> 4) & 0x3FFF);
}

// ---------------- PTX wrappers ----------------
__device__ __forceinline__ void cp16(uint32_t dst, const void* src) {
    asm volatile("cp.async.cg.shared.global [%0], [%1], 16;" :: "r"(dst), "l"(src));
}
__device__ __forceinline__ void cp_commit() {
    asm volatile("cp.async.commit_group;" ::: "memory");
}
template <int N>
__device__ __forceinline__ void cp_wait() {
    asm volatile("cp.async.wait_group %0;" :: "n"(N) : "memory");
}
__device__ __forceinline__ void mbar_init(uint32_t a, uint32_t cnt) {
    asm volatile("mbarrier.init.shared.b64 [%0], %1;" :: "r"(a), "r"(cnt) : "memory");
}
__device__ __forceinline__ void mbar_wait(uint32_t a, uint32_t parity) {
    asm volatile(
        "{\n\t.reg .pred P;\n\t"
        "MW_%=:\n\t"
        "mbarrier.try_wait.parity.acquire.cta.shared::cta.b64 P, [%0], %1;\n\t"
        "@!P bra MW_%=;\n\t}"
        :: "r"(a), "r"(parity) : "memory");
}
#define FENCE_ASYNC() asm volatile("fence.proxy.async.shared::cta;" ::: "memory")

#if TC_OK
__device__ __forceinline__ void tc_commit(uint32_t mbar) {
    asm volatile(
        "tcgen05.commit.cta_group::1.mbarrier::arrive::one.shared::cluster.b64 [%0];"
        :: "r"(mbar) : "memory");
}
__device__ __forceinline__ void mma_f16_ss(uint32_t d, uint64_t a_desc, uint64_t b_desc,
                                           uint32_t idesc, uint32_t accum) {
    asm volatile(
        "{\n\t.reg .pred p;\n\t"
        "setp.ne.u32 p, %4, 0;\n\t"
        "tcgen05.mma.cta_group::1.kind::f16 [%0], %1, %2, %3, {%5, %5, %5, %5}, p;\n\t}"
        :: "r"(d), "l"(a_desc), "l"(b_desc), "r"(idesc), "r"(accum), "r"(0u)
        : "memory");
}
#define TC_ALLOC(saddr, n) \
    asm volatile("tcgen05.alloc.cta_group::1.sync.aligned.shared::cta.b32 [%0], %1;" \
                 :: "r"(saddr), "r"((uint32_t)(n)) : "memory")
#define TC_RELINQ() \
    asm volatile("tcgen05.relinquish_alloc_permit.cta_group::1.sync.aligned;")
#define TC_DEALLOC(t, n) \
    asm volatile("tcgen05.dealloc.cta_group::1.sync.aligned.b32 %0, %1;" :: "r"(t), "r"((uint32_t)(n)))
#define TC_FENCE_AFTER()  asm volatile("tcgen05.fence::after_thread_sync;" ::: "memory")
#define TC_WAIT_LD()      asm volatile("tcgen05.wait::ld.sync.aligned;" ::: "memory")

#define LDTM_X32(r, addr) \
    asm volatile( \
        "tcgen05.ld.sync.aligned.32x32b.x32.b32 " \
        "{%0, %1, %2, %3, %4, %5, %6, %7, " \
        " %8, %9, %10, %11, %12, %13, %14, %15, " \
        " %16, %17, %18, %19, %20, %21, %22, %23, " \
        " %24, %25, %26, %27, %28, %29, %30, %31}, [%32];" \
        : "=r"((r)[0]),  "=r"((r)[1]),  "=r"((r)[2]),  "=r"((r)[3]), \
          "=r"((r)[4]),  "=r"((r)[5]),  "=r"((r)[6]),  "=r"((r)[7]), \
          "=r"((r)[8]),  "=r"((r)[9]),  "=r"((r)[10]), "=r"((r)[11]), \
          "=r"((r)[12]), "=r"((r)[13]), "=r"((r)[14]), "=r"((r)[15]), \
          "=r"((r)[16]), "=r"((r)[17]), "=r"((r)[18]), "=r"((r)[19]), \
          "=r"((r)[20]), "=r"((r)[21]), "=r"((r)[22]), "=r"((r)[23]), \
          "=r"((r)[24]), "=r"((r)[25]), "=r"((r)[26]), "=r"((r)[27]), \
          "=r"((r)[28]), "=r"((r)[29]), "=r"((r)[30]), "=r"((r)[31]) \
        : "r"(addr))
#endif  // TC_OK

// ---------------- stage 0: abs-mean of weights (float4) ----------------
__global__ void absmean_partial_kernel(const float* __restrict__ w, int n, int slot) {
    float s = 0.f;
    const float4* w4 = reinterpret_cast<const float4*>(w);
    int n4 = n >> 2;
    int stride = gridDim.x * blockDim.x;
    for (int i = blockIdx.x * blockDim.x + threadIdx.x; i < n4; i += stride) {
        float4 v = w4[i];
        s += fabsf(v.x) + fabsf(v.y) + fabsf(v.z) + fabsf(v.w);
    }
    s = block_sum_256(s);
    if (threadIdx.x == 0) g_partial[slot][blockIdx.x] = s;
}
__global__ void finalize_scales_kernel(int n1, int n2) {
    for (int slot = 0; slot < 2; slot++) {
        float v = g_partial[slot][threadIdx.x];
        float tot = block_sum_256(v);
        if (threadIdx.x == 0) {
            float mean = tot / (float)(slot == 0 ? n1 : n2);
            mean = fmaxf(mean, 1e-5f);
            g_mul[slot]   = mean;
            g_scale[slot] = 1.0f / mean;
        }
        __syncthreads();
    }
}

// ---------------- stage 1: ternary quantization -> bf16 (float4) ----------------
__global__ void quant_kernel(const float* __restrict__ w, __nv_bfloat16* __restrict__ t,
                             const float* __restrict__ scalep, int n) {
    float s = *scalep;
    const float4* w4 = reinterpret_cast<const float4*>(w);
    __nv_bfloat162* t2 = reinterpret_cast<__nv_bfloat162*>(t);
    int n4 = n >> 2;
    int stride = gridDim.x * blockDim.x;
    for (int i = blockIdx.x * blockDim.x + threadIdx.x; i < n4; i += stride) {
        float4 v = w4[i];
        float q0 = fmaxf(-1.f, fminf(1.f, rintf(v.x * s)));
        float q1 = fmaxf(-1.f, fminf(1.f, rintf(v.y * s)));
        float q2 = fmaxf(-1.f, fminf(1.f, rintf(v.z * s)));
        float q3 = fmaxf(-1.f, fminf(1.f, rintf(v.w * s)));
        t2[i * 2 + 0] = __floats2bfloat162_rn(q0, q1);
        t2[i * 2 + 1] = __floats2bfloat162_rn(q2, q3);
    }
}

// ---------------- LayerNorm with bf16 hi/lo split output (float4, single read) ----
template <int NV4>   // D = NV4 * 4 * 256
__global__ __launch_bounds__(256) void ln_split_kernel(
    const float* __restrict__ x, __nv_bfloat16* __restrict__ hi, __nv_bfloat16* __restrict__ lo,
    const float* __restrict__ gamma, const float* __restrict__ beta)
{
    constexpr int D = NV4 * 1024;
    const int row = blockIdx.x;
    const float4* xr = reinterpret_cast<const float4*>(x + (size_t)row * D);
    float4 v[NV4];
    float s = 0.f, sq = 0.f;
#pragma unroll
    for (int i = 0; i < NV4; i++) {
        v[i] = xr[threadIdx.x + i * 256];
        s  += v[i].x + v[i].y + v[i].z + v[i].w;
        sq += v[i].x * v[i].x + v[i].y * v[i].y + v[i].z * v[i].z + v[i].w * v[i].w;
    }
    __shared__ float sh[16];
    float ws = warp_sum(s), wq = warp_sum(sq);
    if ((threadIdx.x & 31) == 0) { sh[threadIdx.x >> 5] = ws; sh[8 + (threadIdx.x >> 5)] = wq; }
    __syncthreads();
    __shared__ float s_mu, s_rstd;
    if (threadIdx.x == 0) {
        float ts = 0.f, tq = 0.f;
#pragma unroll
        for (int i = 0; i < 8; i++) { ts += sh[i]; tq += sh[8 + i]; }
        float mu = ts / (float)D;
        float var = tq / (float)D - mu * mu;
        s_mu = mu;
        s_rstd = rsqrtf(var + 1e-5f);
    }
    __syncthreads();
    const float mu = s_mu, rstd = s_rstd;
    const float4* g4 = reinterpret_cast<const float4*>(gamma);
    const float4* b4 = reinterpret_cast<const float4*>(beta);
    __nv_bfloat162* hi2 = reinterpret_cast<__nv_bfloat162*>(hi + (size_t)row * D);
    __nv_bfloat162* lo2 = reinterpret_cast<__nv_bfloat162*>(lo + (size_t)row * D);
#pragma unroll
    for (int i = 0; i < NV4; i++) {
        int idx = threadIdx.x + i * 256;
        float4 g = g4[idx], b = b4[idx];
        float o0 = (v[i].x - mu) * rstd * g.x + b.x;
        float o1 = (v[i].y - mu) * rstd * g.y + b.y;
        float o2 = (v[i].z - mu) * rstd * g.z + b.z;
        float o3 = (v[i].w - mu) * rstd * g.w + b.w;
        __nv_bfloat16 h0 = __float2bfloat16(o0), h1 = __float2bfloat16(o1);
        __nv_bfloat16 h2 = __float2bfloat16(o2), h3 = __float2bfloat16(o3);
        hi2[idx * 2 + 0] = __nv_bfloat162(h0, h1);
        hi2[idx * 2 + 1] = __nv_bfloat162(h2, h3);
        lo2[idx * 2 + 0] = __floats2bfloat162_rn(o0 - __bfloat162float(h0),
                                                 o1 - __bfloat162float(h1));
        lo2[idx * 2 + 1] = __floats2bfloat162_rn(o2 - __bfloat162float(h2),
                                                 o3 - __bfloat162float(h3));
    }
}

// ---------------- GEMM: C[M,N] = ((Ahi+Alo)[M,K] . B[N,K]^T)*mul + bias (+GELU) ----------
// 128x256 block tile via two N=128 MMAs; BK=64, cp.async double buffer.
#define BM 128
#define BN 256
#define BK 64
#define TILE_A       16384                 // 128 rows x 128B
#define TILE_B       32768                 // 256 rows x 128B
#define STAGE_BYTES  (2 * TILE_A + TILE_B) // Ahi, Alo, B  = 64KB
#define SM_TMEMPTR   (2 * STAGE_BYTES)     // 131072
#define SM_MBAR0     (SM_TMEMPTR + 8)
#define SM_MBAR1     (SM_TMEMPTR + 16)
#define SMEM_TOTAL   (SM_TMEMPTR + 64)
// idesc: f32 accum, bf16 A/B, N=128, M=128
#define MMA_IDESC 0x8200490u

__device__ __forceinline__ void load_chunk(
    const __nv_bfloat16* __restrict__ Ahi, const __nv_bfloat16* __restrict__ Alo,
    const __nv_bfloat16* __restrict__ Bt, int K, int bm, int bn, int k0, uint32_t sbase)
{
    const int t = threadIdx.x;
#pragma unroll
    for (int i = 0; i < 4; i++) {
        int idx = t + (i << 8);   // 0..1023 : A rows 0..127, 8 chunks each
        int row = idx >> 3;
        int c   = idx & 7;
        uint32_t sw = SW128(row * 128 + c * 16);
        size_t ea = (size_t)(bm + row) * K + k0 + c * 8;
        cp16(sbase + sw,          Ahi + ea);
        cp16(sbase + TILE_A + sw, Alo + ea);
    }
#pragma unroll
    for (int i = 0; i < 8; i++) {
        int idx = t + (i << 8);   // 0..2047 : B rows 0..255, 8 chunks each
        int row = idx >> 3;
        int c   = idx & 7;
        uint32_t sw = SW128(row * 128 + c * 16);
        size_t eb = (size_t)(bn + row) * K + k0 + c * 8;
        cp16(sbase + 2 * TILE_A + sw, Bt + eb);
    }
}

__global__ __launch_bounds__(256)
void gemm_tc_kernel(const __nv_bfloat16* __restrict__ Ahi, const __nv_bfloat16* __restrict__ Alo,
                    const __nv_bfloat16* __restrict__ Bt,  const float* __restrict__ bias,
                    const float* __restrict__ mulp, float* __restrict__ C,
                    int M, int N, int K, int do_gelu)
{
#if TC_OK
    extern __shared__ char smem[];
    const uint32_t sb  = smem_u32(smem);
    const int tid = threadIdx.x, wid = tid >> 5, lid = tid & 31;
    const int bm = blockIdx.y * BM, bn = blockIdx.x * BN;

    if (wid == 0) { TC_ALLOC(sb + SM_TMEMPTR, 256); TC_RELINQ(); }
    if (tid == 0) { mbar_init(sb + SM_MBAR0, 1); mbar_init(sb + SM_MBAR1, 1); }
    __syncthreads();
    uint32_t tmem;
    asm volatile("ld.shared.b32 %0, [%1];" : "=r"(tmem) : "r"(sb + SM_TMEMPTR));

    const float mul = *mulp;
    const int nk = K / BK;

    uint64_t ad[2], ld_[2], bd0[2], bd1[2];
#pragma unroll
    for (int s = 0; s < 2; s++) {
        uint32_t base = sb + s * STAGE_BYTES;
        ad[s]  = make_desc(base);
        ld_[s] = make_desc(base + TILE_A);
        bd0[s] = make_desc(base + 2 * TILE_A);
        bd1[s] = make_desc(base + 2 * TILE_A + 16384);   // B rows 128..255
    }

    load_chunk(Ahi, Alo, Bt, K, bm, bn, 0, sb);                cp_commit();
    load_chunk(Ahi, Alo, Bt, K, bm, bn, BK, sb + STAGE_BYTES); cp_commit();

    int wcnt0 = 0, wcnt1 = 0;
    for (int i = 0; i < nk; i++) {
        const int b = i & 1;
        if (i + 1 < nk) cp_wait<1>(); else cp_wait<0>();
        FENCE_ASYNC();
        __syncthreads();
        if (tid == 0) {
#pragma unroll
            for (int j = 0; j < 4; j++) {
                uint32_t first = (i > 0) || (j > 0);
                mma_f16_ss(tmem,       ad[b]  + j * 2, bd0[b] + j * 2, MMA_IDESC, first);
                mma_f16_ss(tmem,       ld_[b] + j * 2, bd0[b] + j * 2, MMA_IDESC, 1u);
                mma_f16_ss(tmem + 128, ad[b]  + j * 2, bd1[b] + j * 2, MMA_IDESC, first);
                mma_f16_ss(tmem + 128, ld_[b] + j * 2, bd1[b] + j * 2, MMA_IDESC, 1u);
            }
            tc_commit(sb + SM_MBAR0 + b * 8);
        }
        if (i + 2 < nk) {
            if (b == 0) { mbar_wait(sb + SM_MBAR0, wcnt0 & 1); wcnt0++; }
            else        { mbar_wait(sb + SM_MBAR1, wcnt1 & 1); wcnt1++; }
            load_chunk(Ahi, Alo, Bt, K, bm, bn, (i + 2) * BK, sb + b * STAGE_BYTES);
            cp_commit();
        }
    }
    mbar_wait(sb + SM_MBAR0, wcnt0 & 1);
    mbar_wait(sb + SM_MBAR1, wcnt1 & 1);
    TC_FENCE_AFTER();

    // epilogue: 8 warps. warps 0-3 -> cols 0..127, warps 4-7 -> cols 128..255.
    {
        const int half = wid >> 2;             // 0 or 1
        const int sp   = wid & 3;              // subpartition
        const int row  = bm + sp * 32 + lid;
        const int cbase = bn + half * 128;
        float* crow = C + (size_t)row * N + cbase;
        const uint32_t tb = tmem + half * 128;
#pragma unroll
        for (int c0 = 0; c0 < 128; c0 += 32) {
            uint32_t r[32];
            LDTM_X32(r, tb + c0);
            TC_WAIT_LD();
#pragma unroll
            for (int j = 0; j < 32; j += 4) {
                float4 v4;
                float v0 = __uint_as_float(r[j + 0]) * mul + bias[cbase + c0 + j + 0];
                float v1 = __uint_as_float(r[j + 1]) * mul + bias[cbase + c0 + j + 1];
                float v2 = __uint_as_float(r[j + 2]) * mul + bias[cbase + c0 + j + 2];
                float v3 = __uint_as_float(r[j + 3]) * mul + bias[cbase + c0 + j + 3];
                if (do_gelu) {
                    v0 = 0.5f * v0 * (1.0f + erff(v0 * 0.70710678118654752f));
                    v1 = 0.5f * v1 * (1.0f + erff(v1 * 0.70710678118654752f));
                    v2 = 0.5f * v2 * (1.0f + erff(v2 * 0.70710678118654752f));
                    v3 = 0.5f * v3 * (1.0f + erff(v3 * 0.70710678118654752f));
                }
                v4.x = v0; v4.y = v1; v4.z = v2; v4.w = v3;
                *reinterpret_cast<float4*>(crow + c0 + j) = v4;
            }
        }
    }
    __syncthreads();
    if (wid == 0) TC_DEALLOC(tmem, 256);

#else
    // ============ SIMT fallback (correct on any arch; never used on GB300) ============
    extern __shared__ char smem[];
    float (*As)[128] = reinterpret_cast<float (*)[128]>(smem);
    float (*Bs)[128] = reinterpret_cast<float (*)[128]>(smem + 16 * 128 * 4);
    const int bm = blockIdx.y * BM;
    const int tid = threadIdx.x;
    const int tr = tid >> 4, tc = tid & 15;
    const float mul = *mulp;

    for (int hblk = 0; hblk < 2; hblk++) {
        const int bn = blockIdx.x * BN + hblk * 128;
        float acc[8][8];
#pragma unroll
        for (int i = 0; i < 8; i++)
#pragma unroll
            for (int j = 0; j < 8; j++) acc[i][j] = 0.f;
        for (int k0 = 0; k0 < K; k0 += 16) {
#pragma unroll
            for (int it = 0; it < 8; it++) {
                int idx = tid + it * 256;
                int row = idx >> 4, c = idx & 15;
                size_t ea = (size_t)(bm + row) * K + k0 + c;
                As[c][row] = __bfloat162float(Ahi[ea]) + __bfloat162float(Alo[ea]);
                size_t eb = (size_t)(bn + row) * K + k0 + c;
                Bs[c][row] = __bfloat162float(Bt[eb]);
            }
            __syncthreads();
#pragma unroll
            for (int k = 0; k < 16; k++) {
                float a[8], b[8];
#pragma unroll
                for (int i = 0; i < 4; i++) { a[i] = As[k][tr*4+i]; a[4+i] = As[k][64+tr*4+i]; }
#pragma unroll
                for (int j = 0; j < 4; j++) { b[j] = Bs[k][tc*4+j]; b[4+j] = Bs[k][64+tc*4+j]; }
#pragma unroll
                for (int i = 0; i < 8; i++)
#pragma unroll
                    for (int j = 0; j < 8; j++)
                        acc[i][j] = fmaf(a[i], b[j], acc[i][j]);
            }
            __syncthreads();
        }
#pragma unroll
        for (int i = 0; i < 8; i++) {
            int gr = bm + ((i < 4) ? (tr*4+i) : (64 + tr*4 + i - 4));
#pragma unroll
            for (int j = 0; j < 8; j++) {
                int gc = bn + ((j < 4) ? (tc*4+j) : (64 + tc*4 + j - 4));
                float v = acc[i][j] * mul + bias[gc];
                if (do_gelu) v = 0.5f * v * (1.0f + erff(v * 0.70710678118654752f));
                C[(size_t)gr * N + gc] = v;
            }
        }
        __syncthreads();
    }
#endif
}

// ---------------- launcher ----------------
extern "C" void kernel_launch(void* const* d_in, const int* in_sizes, int n_in,
                              void* d_out, int out_size)
{
    const float* x    = (const float*)d_in[0];
    const float* ln1g = (const float*)d_in[1];
    const float* ln1b = (const float*)d_in[2];
    const float* w1   = (const float*)d_in[3];
    const float* b1   = (const float*)d_in[4];
    const float* ln2g = (const float*)d_in[5];
    const float* ln2b = (const float*)d_in[6];
    const float* w2   = (const float*)d_in[7];
    const float* b2   = (const float*)d_in[8];
    float* out = (float*)d_out;

    __nv_bfloat16 *xhi, *xlo, *hhi, *hlo, *t1, *t2;
    float *h, *scale, *mul;
    cudaGetSymbolAddress((void**)&xhi,   g_xhi);
    cudaGetSymbolAddress((void**)&xlo,   g_xlo);
    cudaGetSymbolAddress((void**)&h,     g_h);
    cudaGetSymbolAddress((void**)&hhi,   g_hhi);
    cudaGetSymbolAddress((void**)&hlo,   g_hlo);
    cudaGetSymbolAddress((void**)&t1,    g_t1);
    cudaGetSymbolAddress((void**)&t2,    g_t2);
    cudaGetSymbolAddress((void**)&scale, g_scale);
    cudaGetSymbolAddress((void**)&mul,   g_mul);

    static int smem_set = 0;
    if (!smem_set) {
        cudaFuncSetAttribute(gemm_tc_kernel, cudaFuncAttributeMaxDynamicSharedMemorySize,
                             SMEM_TOTAL);
        smem_set = 1;
    }

    // 1) scales
    absmean_partial_kernel<<<256, 256>>>(w1, HID * DIM, 0);
    absmean_partial_kernel<<<256, 256>>>(w2, DIM * HID, 1);
    finalize_scales_kernel<<<1, 256>>>(HID * DIM, DIM * HID);

    // 2) ternary quantization -> bf16 (exact)
    quant_kernel<<<512, 256>>>(w1, t1, scale + 0, HID * DIM);
    quant_kernel<<<512, 256>>>(w2, t2, scale + 1, DIM * HID);

    // 3) LN1 -> bf16 hi/lo split
    ln_split_kernel<1><<<TOK, 256>>>(x, xhi, xlo, ln1g, ln1b);

    // 4) GEMM1 + bias + exact GELU  (M=8192, N=4096, K=1024)
    gemm_tc_kernel<<<dim3(HID / BN, TOK / BM), 256, SMEM_TOTAL>>>(
        xhi, xlo, t1, b1, mul + 0, h, TOK, HID, DIM, 1);

    // 5) LN2 -> bf16 hi/lo split
    ln_split_kernel<4><<<TOK, 256>>>(h, hhi, hlo, ln2g, ln2b);

    // 6) GEMM2 + bias  (M=8192, N=1024, K=4096)
    gemm_tc_kernel<<<dim3(DIM / BN, TOK / BM), 256, SMEM_TOTAL>>>(
        hhi, hlo, t2, b2, mul + 1, out, TOK, DIM, HID, 0);
}